// round 1
// baseline (speedup 1.0000x reference)
#include <cuda_runtime.h>
#include <cuda_bf16.h>
#include <stdint.h>

// HSTUBlockPostprocessor: jagged gather of candidate rows + row-wise L2 norm.
//
// Inputs (metadata order):
//   d_in[0] : values                  float32  [L, D]  (L = sum(seqlen), D = 512)
//   d_in[1] : seqlen_offsets          int32    [B+1]
//   d_in[2] : num_candidates_offsets  int32    [B+1]
//   d_in[3] : total_candidates        int32    [1]     (scalar, device-side; not needed)
//
// Output: emb [total_candidates, D] float32, optionally followed by
//   seqlen (B floats) and num_candidates_offsets (B+1 floats) if the harness
//   concatenates all reference outputs (detected via out_size % D).
//
// Index simplification:
//   src_row = seqlen_offsets[seg+1] - num_candidates_offsets[seg+1] + idx
// where seg is such that nc[seg] <= idx < nc[seg+1].

#define D_DIM 512
#define VEC_PER_ROW (D_DIM / 4)   // 128 float4 per row
#define WARPS_PER_BLOCK 8
#define THREADS_PER_BLOCK (WARPS_PER_BLOCK * 32)

__global__ __launch_bounds__(THREADS_PER_BLOCK)
void hstu_gather_l2norm_kernel(const float* __restrict__ values,
                               const int* __restrict__ seqlen_offsets,
                               const int* __restrict__ nc_offsets,
                               float* __restrict__ out,
                               int n_rows, int n_seg) {
    const int warp_id = (blockIdx.x * WARPS_PER_BLOCK) + (threadIdx.x >> 5);
    if (warp_id >= n_rows) return;
    const int lane = threadIdx.x & 31;
    const int idx = warp_id;  // flat candidate row index

    // Branchless binary search: find seg with nc[seg] <= idx < nc[seg+1].
    // All lanes compute redundantly (L1-resident, ~7 iterations for B=128).
    int lo = 0, hi = n_seg;  // seg in [0, n_seg)
    while (lo < hi) {
        int mid = (lo + hi) >> 1;
        // nc[mid+1] > idx ? keep left : go right
        if (__ldg(&nc_offsets[mid + 1]) > idx) hi = mid; else lo = mid + 1;
    }
    const int seg = lo;
    const long long src_row =
        (long long)(__ldg(&seqlen_offsets[seg + 1]) - __ldg(&nc_offsets[seg + 1])) + idx;

    const float4* __restrict__ src =
        reinterpret_cast<const float4*>(values + src_row * (long long)D_DIM);
    float4* __restrict__ dst =
        reinterpret_cast<float4*>(out + (long long)idx * D_DIM);

    // Each lane: 4 float4 loads at stride 32 (coalesced 128B per instruction).
    float4 v0 = src[lane];
    float4 v1 = src[lane + 32];
    float4 v2 = src[lane + 64];
    float4 v3 = src[lane + 96];

    float ss = v0.x * v0.x + v0.y * v0.y + v0.z * v0.z + v0.w * v0.w;
    ss += v1.x * v1.x + v1.y * v1.y + v1.z * v1.z + v1.w * v1.w;
    ss += v2.x * v2.x + v2.y * v2.y + v2.z * v2.z + v2.w * v2.w;
    ss += v3.x * v3.x + v3.y * v3.y + v3.z * v3.z + v3.w * v3.w;

    // Warp-level reduction (butterfly).
    #pragma unroll
    for (int off = 16; off > 0; off >>= 1)
        ss += __shfl_xor_sync(0xFFFFFFFFu, ss, off);

    const float scale = 1.0f / fmaxf(sqrtf(ss), 1e-6f);

    v0.x *= scale; v0.y *= scale; v0.z *= scale; v0.w *= scale;
    v1.x *= scale; v1.y *= scale; v1.z *= scale; v1.w *= scale;
    v2.x *= scale; v2.y *= scale; v2.z *= scale; v2.w *= scale;
    v3.x *= scale; v3.y *= scale; v3.z *= scale; v3.w *= scale;

    dst[lane]      = v0;
    dst[lane + 32] = v1;
    dst[lane + 64] = v2;
    dst[lane + 96] = v3;
}

// Tail: seqlen (B floats) then num_candidates_offsets (B+1 floats), if present.
__global__ void hstu_tail_kernel(const int* __restrict__ nc_offsets,
                                 float* __restrict__ out_tail, int n_seg) {
    int i = blockIdx.x * blockDim.x + threadIdx.x;
    if (i < n_seg)
        out_tail[i] = (float)(nc_offsets[i + 1] - nc_offsets[i]);
    if (i <= n_seg)
        out_tail[n_seg + i] = (float)nc_offsets[i];
}

extern "C" void kernel_launch(void* const* d_in, const int* in_sizes, int n_in,
                              void* d_out, int out_size) {
    const float* values = (const float*)d_in[0];
    const int* seqlen_offsets = (const int*)d_in[1];
    const int* nc_offsets = (const int*)d_in[2];
    float* out = (float*)d_out;

    const int n_seg = in_sizes[2] - 1;  // B

    // Detect whether out_size includes the (seqlen, offsets) tail.
    long long emb_elems = out_size;
    bool has_tail = false;
    long long tail = 2LL * n_seg + 1;
    if ((long long)out_size % D_DIM != 0 &&
        ((long long)out_size - tail) % D_DIM == 0 && (long long)out_size > tail) {
        emb_elems = (long long)out_size - tail;
        has_tail = true;
    }
    const int n_rows = (int)(emb_elems / D_DIM);

    const int blocks = (n_rows + WARPS_PER_BLOCK - 1) / WARPS_PER_BLOCK;
    hstu_gather_l2norm_kernel<<<blocks, THREADS_PER_BLOCK>>>(
        values, seqlen_offsets, nc_offsets, out, n_rows, n_seg);

    if (has_tail) {
        int t = 256;
        int b = (n_seg + 1 + t - 1) / t;
        hstu_tail_kernel<<<b, t>>>(nc_offsets, out + emb_elems, n_seg);
    }
}

// round 2
// speedup vs baseline: 1.1444x; 1.1444x over previous
#include <cuda_runtime.h>
#include <cuda_bf16.h>
#include <stdint.h>

// HSTUBlockPostprocessor: jagged gather of candidate rows + row-wise L2 norm.
//
// Inputs (metadata order):
//   d_in[0] : values                  float32  [L, D]  (D = 512)
//   d_in[1] : seqlen_offsets          int32    [B+1]
//   d_in[2] : num_candidates_offsets  int32    [B+1]
//   d_in[3] : total_candidates        int32    [1]
//
// Output: emb [total_candidates, 512] float32, followed by
//   seqlen (B floats) and num_candidates_offsets (B+1 floats) — tail fused
//   into the main kernel (block 0) to avoid a second graph node (~4us).
//
// src_row = seqlen_offsets[seg+1] - num_candidates_offsets[seg+1] + idx,
// with seg s.t. nc[seg] <= idx < nc[seg+1].

#define D_DIM 512
#define WARPS_PER_BLOCK 8
#define THREADS_PER_BLOCK (WARPS_PER_BLOCK * 32)

__global__ __launch_bounds__(THREADS_PER_BLOCK)
void hstu_gather_l2norm_kernel(const float* __restrict__ values,
                               const int* __restrict__ seqlen_offsets,
                               const int* __restrict__ nc_offsets,
                               float* __restrict__ out,
                               int n_rows, int n_seg,
                               float* __restrict__ out_tail) {
    // ── Fused tail write (block 0 only; 257 elements, cheap) ──
    if (out_tail != nullptr && blockIdx.x == 0) {
        for (int i = threadIdx.x; i <= n_seg; i += THREADS_PER_BLOCK) {
            int nc_i = __ldg(&nc_offsets[i]);
            if (i < n_seg)
                out_tail[i] = (float)(__ldg(&nc_offsets[i + 1]) - nc_i);
            out_tail[n_seg + i] = (float)nc_i;
        }
    }

    const int warp_id = (blockIdx.x * WARPS_PER_BLOCK) + (threadIdx.x >> 5);
    if (warp_id >= n_rows) return;
    const int lane = threadIdx.x & 31;
    const int idx = warp_id;  // flat candidate row index

    // Binary search: seg with nc[seg] <= idx < nc[seg+1]. L1-resident.
    int lo = 0, hi = n_seg;
    while (lo < hi) {
        int mid = (lo + hi) >> 1;
        if (__ldg(&nc_offsets[mid + 1]) > idx) hi = mid; else lo = mid + 1;
    }
    const int seg = lo;
    const long long src_row =
        (long long)(__ldg(&seqlen_offsets[seg + 1]) - __ldg(&nc_offsets[seg + 1])) + idx;

    const float4* __restrict__ src =
        reinterpret_cast<const float4*>(values + src_row * (long long)D_DIM);
    float4* __restrict__ dst =
        reinterpret_cast<float4*>(out + (long long)idx * D_DIM);

    // 4 independent 128-bit streaming loads per lane (coalesced 128B/instr,
    // evict-first: single-touch data, keep it out of L2's way).
    float4 v0 = __ldcs(&src[lane]);
    float4 v1 = __ldcs(&src[lane + 32]);
    float4 v2 = __ldcs(&src[lane + 64]);
    float4 v3 = __ldcs(&src[lane + 96]);

    float ss = v0.x * v0.x + v0.y * v0.y + v0.z * v0.z + v0.w * v0.w;
    ss += v1.x * v1.x + v1.y * v1.y + v1.z * v1.z + v1.w * v1.w;
    ss += v2.x * v2.x + v2.y * v2.y + v2.z * v2.z + v2.w * v2.w;
    ss += v3.x * v3.x + v3.y * v3.y + v3.z * v3.z + v3.w * v3.w;

    #pragma unroll
    for (int off = 16; off > 0; off >>= 1)
        ss += __shfl_xor_sync(0xFFFFFFFFu, ss, off);

    const float scale = 1.0f / fmaxf(sqrtf(ss), 1e-6f);

    v0.x *= scale; v0.y *= scale; v0.z *= scale; v0.w *= scale;
    v1.x *= scale; v1.y *= scale; v1.z *= scale; v1.w *= scale;
    v2.x *= scale; v2.y *= scale; v2.z *= scale; v2.w *= scale;
    v3.x *= scale; v3.y *= scale; v3.z *= scale; v3.w *= scale;

    __stcs(&dst[lane],      v0);
    __stcs(&dst[lane + 32], v1);
    __stcs(&dst[lane + 64], v2);
    __stcs(&dst[lane + 96], v3);
}

extern "C" void kernel_launch(void* const* d_in, const int* in_sizes, int n_in,
                              void* d_out, int out_size) {
    const float* values = (const float*)d_in[0];
    const int* seqlen_offsets = (const int*)d_in[1];
    const int* nc_offsets = (const int*)d_in[2];
    float* out = (float*)d_out;

    const int n_seg = in_sizes[2] - 1;  // B

    // Detect whether out_size includes the (seqlen, offsets) tail.
    long long emb_elems = out_size;
    float* out_tail = nullptr;
    long long tail = 2LL * n_seg + 1;
    if ((long long)out_size % D_DIM != 0 &&
        ((long long)out_size - tail) % D_DIM == 0 && (long long)out_size > tail) {
        emb_elems = (long long)out_size - tail;
        out_tail = out + emb_elems;
    }
    const int n_rows = (int)(emb_elems / D_DIM);

    const int blocks = (n_rows + WARPS_PER_BLOCK - 1) / WARPS_PER_BLOCK;
    hstu_gather_l2norm_kernel<<<blocks, THREADS_PER_BLOCK>>>(
        values, seqlen_offsets, nc_offsets, out, n_rows, n_seg, out_tail);
}